// round 14
// baseline (speedup 1.0000x reference)
#include <cuda_runtime.h>
#include <cuda_bf16.h>
#include <math.h>
#include <stdint.h>

// Problem dims
#define BB 2
#define SS 1024
#define DD 1024
#define HH 16
#define HD 64
#define LL 3
#define FF 4096
#define VV 32000
#define MROWS (BB*SS)   // 2048

// ===================== PTX helpers (sm_80-class only: ldmatrix/mma/cp.async) ==
__device__ __forceinline__ uint32_t smem_u32(const void* p) {
    uint32_t a;
    asm("{ .reg .u64 t; cvta.to.shared.u64 t, %1; cvt.u32.u64 %0, t; }" : "=r"(a) : "l"(p));
    return a;
}
__device__ __forceinline__ void ldsm_x4(uint32_t& r0, uint32_t& r1, uint32_t& r2, uint32_t& r3, uint32_t addr) {
    asm volatile("ldmatrix.sync.aligned.m8n8.x4.shared.b16 {%0,%1,%2,%3}, [%4];"
        : "=r"(r0), "=r"(r1), "=r"(r2), "=r"(r3) : "r"(addr));
}
__device__ __forceinline__ void mma_bf16(float* d, const uint32_t* a, const uint32_t* b) {
    asm volatile("mma.sync.aligned.m16n8k16.row.col.f32.bf16.bf16.f32 "
        "{%0,%1,%2,%3}, {%4,%5,%6,%7}, {%8,%9}, {%0,%1,%2,%3};"
        : "+f"(d[0]), "+f"(d[1]), "+f"(d[2]), "+f"(d[3])
        : "r"(a[0]), "r"(a[1]), "r"(a[2]), "r"(a[3]), "r"(b[0]), "r"(b[1]));
}
__device__ __forceinline__ void cp_async16(uint32_t saddr, const void* gaddr) {
    asm volatile("cp.async.cg.shared.global [%0], [%1], 16;" :: "r"(saddr), "l"(gaddr));
}
#define CP_COMMIT() asm volatile("cp.async.commit_group;" ::: "memory")
#define CP_WAIT2()  asm volatile("cp.async.wait_group 2;" ::: "memory")
#define CP_WAIT0()  asm volatile("cp.async.wait_group 0;" ::: "memory")

// ===================== device scratch (no allocations) =====================
__device__ float g_h  [MROWS*DD];
__device__ float g_qkv[MROWS*3*DD];
__device__ float g_bqkv[LL*3*DD];
__device__ int   g_is64;

__device__ __nv_bfloat16 g_ainh[MROWS*DD], g_ainl[MROWS*DD];
__device__ __nv_bfloat16 g_aoh [MROWS*DD], g_aol [MROWS*DD];
__device__ __nv_bfloat16 g_ffnh[MROWS*FF], g_ffnl[MROWS*FF];

__device__ __nv_bfloat16 g_wqkvh[LL*3*DD*DD], g_wqkvl[LL*3*DD*DD];
__device__ __nv_bfloat16 g_woh [LL*DD*DD],   g_wol [LL*DD*DD];
__device__ __nv_bfloat16 g_w1h [LL*FF*DD],   g_w1l [LL*FF*DD];   // [F,D] per layer
__device__ __nv_bfloat16 g_w2h [LL*DD*FF],   g_w2l [LL*DD*FF];   // [D,F] per layer
__device__ __nv_bfloat16 g_wouth[(size_t)VV*DD], g_woutl[(size_t)VV*DD];

// ===================== small kernels =====================
__global__ void detect_kernel(const int* __restrict__ xw) {
    __shared__ int nz;
    if (threadIdx.x == 0) nz = 0;
    __syncthreads();
    int local = 0;
    for (int i = threadIdx.x; i < 1024; i += blockDim.x)
        if (xw[2*i + 1] != 0) local++;
    if (local) atomicAdd(&nz, local);
    __syncthreads();
    if (threadIdx.x == 0) g_is64 = (nz == 0) ? 1 : 0;
}

__global__ void embed_kernel(const void* __restrict__ x,
                             const float* __restrict__ tok,
                             const float* __restrict__ pos,
                             float* __restrict__ h) {
    int bs = blockIdx.x;
    int s  = bs & (SS - 1);
    long long tokid = g_is64 ? ((const long long*)x)[bs]
                             : (long long)((const int*)x)[bs];
    const float4* tr = (const float4*)(tok + (size_t)tokid * DD);
    const float4* pr = (const float4*)(pos + (size_t)s * DD);
    float4*       hr = (float4*)(h + (size_t)bs * DD);
    for (int i = threadIdx.x; i < DD/4; i += blockDim.x) {
        float4 t = tr[i], p = pr[i];
        hr[i] = make_float4(t.x+p.x, t.y+p.y, t.z+p.z, t.w+p.w);
    }
}

// LayerNorm fused with bf16 (hi,lo) split output
__global__ __launch_bounds__(256) void layernorm_split(
        const float* __restrict__ x, const float* __restrict__ g,
        const float* __restrict__ b,
        __nv_bfloat16* __restrict__ yh, __nv_bfloat16* __restrict__ yl) {
    __shared__ float s1[256], s2[256];
    int row = blockIdx.x, tid = threadIdx.x;
    const float4* xr = (const float4*)(x + (size_t)row * DD);
    float4 v = xr[tid];
    float sum = v.x + v.y + v.z + v.w;
    float sq  = v.x*v.x + v.y*v.y + v.z*v.z + v.w*v.w;
    s1[tid] = sum; s2[tid] = sq;
    __syncthreads();
    for (int off = 128; off > 0; off >>= 1) {
        if (tid < off) { s1[tid] += s1[tid+off]; s2[tid] += s2[tid+off]; }
        __syncthreads();
    }
    float mean = s1[0] * (1.0f/DD);
    float var  = s2[0] * (1.0f/DD) - mean*mean;
    float rstd = rsqrtf(var + 1e-5f);
    float4 gg = ((const float4*)g)[tid], bb = ((const float4*)b)[tid];
    float o0 = (v.x-mean)*rstd*gg.x + bb.x;
    float o1 = (v.y-mean)*rstd*gg.y + bb.y;
    float o2 = (v.z-mean)*rstd*gg.z + bb.z;
    float o3 = (v.w-mean)*rstd*gg.w + bb.w;
    __nv_bfloat16 h0 = __float2bfloat16(o0), h1 = __float2bfloat16(o1);
    __nv_bfloat16 h2 = __float2bfloat16(o2), h3 = __float2bfloat16(o3);
    __nv_bfloat162 p0, p1, q0, q1;
    p0.x = h0; p0.y = h1; p1.x = h2; p1.y = h3;
    q0.x = __float2bfloat16(o0 - __bfloat162float(h0));
    q0.y = __float2bfloat16(o1 - __bfloat162float(h1));
    q1.x = __float2bfloat16(o2 - __bfloat162float(h2));
    q1.y = __float2bfloat16(o3 - __bfloat162float(h3));
    size_t base2 = (size_t)row * (DD/2) + tid*2;
    ((__nv_bfloat162*)yh)[base2]   = p0;
    ((__nv_bfloat162*)yh)[base2+1] = p1;
    ((__nv_bfloat162*)yl)[base2]   = q0;
    ((__nv_bfloat162*)yl)[base2+1] = q1;
}

// transpose + split: in [K,N] fp32 (layer-strided) -> out [N,K] bf16 hi/lo
__global__ __launch_bounds__(256) void tsplit(
        const float* __restrict__ in, __nv_bfloat16* __restrict__ oh,
        __nv_bfloat16* __restrict__ ol, int K, int N,
        size_t inLS, size_t outLS) {
    __shared__ float t[32][33];
    int z = blockIdx.z;
    in += (size_t)z * inLS; oh += (size_t)z * outLS; ol += (size_t)z * outLS;
    int nb = blockIdx.x * 32, kb = blockIdx.y * 32;
    int tx = threadIdx.x, ty = threadIdx.y;   // 32 x 8
    #pragma unroll
    for (int r = 0; r < 32; r += 8)
        t[ty+r][tx] = in[(size_t)(kb+ty+r) * N + nb + tx];
    __syncthreads();
    #pragma unroll
    for (int r = 0; r < 32; r += 8) {
        float a = t[tx][ty+r];
        __nv_bfloat16 h = __float2bfloat16(a);
        float lo = a - __bfloat162float(h);
        size_t o = (size_t)(nb+ty+r) * K + kb + tx;
        oh[o] = h; ol[o] = __float2bfloat16(lo);
    }
}

__global__ void packb(const float* __restrict__ bq, const float* __restrict__ bk,
                      const float* __restrict__ bv, float* __restrict__ out) {
    int l = blockIdx.x, t = threadIdx.x;
    out[l*3*DD + t]        = bq[l*DD + t];
    out[l*3*DD + DD + t]   = bk[l*DD + t];
    out[l*3*DD + 2*DD + t] = bv[l*DD + t];
}

// ===================== HMMA bf16x3 GEMM (mma.sync m16n8k16) ==================
// C[M,N] = A @ B^T.  A = Ah+Al [M,K] bf16 row-major; B^T = Bh+Bl [N,K] bf16.
// Block tile 256x128, BK=32, 512 threads = 16 warps (8M x 2N), warp tile 32x64.
// 3-stage cp.async pipeline. SMEM row stride 80B.
// mode 0: C = acc + bias
// mode 1: g = gelu(acc+bias); Oh/Ol = bf16 split(g)
// mode 2: C = acc + bias + addend
#define STG_A_H 0
#define STG_A_L 20480
#define STG_B_H 40960
#define STG_B_L 51200
#define STG_SZ  61440
#define GEMM_SMEM (3*STG_SZ)

__global__ __launch_bounds__(512, 1) void gemm_hmma3(
        const __nv_bfloat16* __restrict__ Ah, const __nv_bfloat16* __restrict__ Al,
        const __nv_bfloat16* __restrict__ Bh, const __nv_bfloat16* __restrict__ Bl,
        const float* __restrict__ bias, const float* __restrict__ addend,
        float* __restrict__ C, __nv_bfloat16* __restrict__ Oh, __nv_bfloat16* __restrict__ Ol,
        int N, int K, int mode) {
    extern __shared__ char smem[];
    uint32_t sb = smem_u32(smem);
    int tid = threadIdx.x, wid = tid >> 5, lane = tid & 31;
    int warp_m = wid & 7, warp_n = wid >> 3;
    int nbase = blockIdx.x * 128, mbase = blockIdx.y * 256;

    const char* Agh = (const char*)(Ah + (size_t)mbase * K);
    const char* Agl = (const char*)(Al + (size_t)mbase * K);
    const char* Bgh = (const char*)(Bh + (size_t)nbase * K);
    const char* Bgl = (const char*)(Bl + (size_t)nbase * K);
    size_t K2 = (size_t)K * 2;

    // A: 1024 16B-chunks per array (256 rows x 4), 2 per thread. B: 512 chunks, 1 per thread.
    int ra0 = tid >> 2,           ca0 = (tid & 3) * 16;
    int ra1 = (tid + 512) >> 2,   ca1 = ((tid + 512) & 3) * 16;
    uint32_t sa0 = (uint32_t)ra0 * 80 + ca0;
    uint32_t sa1 = (uint32_t)ra1 * 80 + ca1;
    int rb = tid >> 2,            cb = (tid & 3) * 16;
    uint32_t sbo = (uint32_t)rb * 80 + cb;

    float acc[2][8][4];
    #pragma unroll
    for (int i = 0; i < 2; i++)
        #pragma unroll
        for (int j = 0; j < 8; j++)
            #pragma unroll
            for (int q = 0; q < 4; q++) acc[i][j][q] = 0.f;

    int nk = K >> 5;

    // prologue: stages 0,1
    #pragma unroll
    for (int s = 0; s < 2; s++) {
        uint32_t st = (uint32_t)s * STG_SZ;
        size_t kb = (size_t)s * 64;
        size_t ga0 = (size_t)ra0 * K2 + kb + ca0;
        size_t ga1 = (size_t)ra1 * K2 + kb + ca1;
        size_t gb  = (size_t)rb  * K2 + kb + cb;
        cp_async16(sb + st + STG_A_H + sa0, Agh + ga0); cp_async16(sb + st + STG_A_H + sa1, Agh + ga1);
        cp_async16(sb + st + STG_A_L + sa0, Agl + ga0); cp_async16(sb + st + STG_A_L + sa1, Agl + ga1);
        cp_async16(sb + st + STG_B_H + sbo, Bgh + gb);
        cp_async16(sb + st + STG_B_L + sbo, Bgl + gb);
        CP_COMMIT();
    }

    for (int c = 0; c < nk; c++) {
        if (c + 2 < nk) {
            uint32_t st = (uint32_t)((c + 2) % 3) * STG_SZ;
            size_t kb = (size_t)(c + 2) * 64;
            size_t ga0 = (size_t)ra0 * K2 + kb + ca0;
            size_t ga1 = (size_t)ra1 * K2 + kb + ca1;
            size_t gb  = (size_t)rb  * K2 + kb + cb;
            cp_async16(sb + st + STG_A_H + sa0, Agh + ga0); cp_async16(sb + st + STG_A_H + sa1, Agh + ga1);
            cp_async16(sb + st + STG_A_L + sa0, Agl + ga0); cp_async16(sb + st + STG_A_L + sa1, Agl + ga1);
            cp_async16(sb + st + STG_B_H + sbo, Bgh + gb);
            cp_async16(sb + st + STG_B_L + sbo, Bgl + gb);
        }
        CP_COMMIT();
        CP_WAIT2();
        __syncthreads();

        uint32_t base = sb + (uint32_t)(c % 3) * STG_SZ;
        #pragma unroll
        for (int ks = 0; ks < 2; ks++) {
            uint32_t ah[2][4], al[2][4];
            #pragma unroll
            for (int mt = 0; mt < 2; mt++) {
                uint32_t ra = base + (uint32_t)(warp_m*32 + mt*16 + (lane & 15)) * 80
                            + (uint32_t)ks*32 + (uint32_t)(lane >> 4) * 16;
                ldsm_x4(ah[mt][0], ah[mt][1], ah[mt][2], ah[mt][3], ra + STG_A_H);
                ldsm_x4(al[mt][0], al[mt][1], al[mt][2], al[mt][3], ra + STG_A_L);
            }
            #pragma unroll
            for (int p = 0; p < 4; p++) {
                uint32_t rbad = base + (uint32_t)(warp_n*64 + p*16 + ((lane >> 4) * 8) + (lane & 7)) * 80
                              + (uint32_t)((lane >> 3) & 1) * 16 + (uint32_t)ks*32;
                uint32_t bh[2][2], bl[2][2];
                uint32_t x0, x1, x2, x3;
                ldsm_x4(x0, x1, x2, x3, rbad + STG_B_H);
                bh[0][0] = x0; bh[0][1] = x1; bh[1][0] = x2; bh[1][1] = x3;
                ldsm_x4(x0, x1, x2, x3, rbad + STG_B_L);
                bl[0][0] = x0; bl[0][1] = x1; bl[1][0] = x2; bl[1][1] = x3;
                #pragma unroll
                for (int mt = 0; mt < 2; mt++)
                    #pragma unroll
                    for (int q = 0; q < 2; q++) {
                        mma_bf16(acc[mt][p*2+q], ah[mt], bh[q]);
                        mma_bf16(acc[mt][p*2+q], ah[mt], bl[q]);
                        mma_bf16(acc[mt][p*2+q], al[mt], bh[q]);
                    }
            }
        }
        __syncthreads();
    }
    CP_WAIT0();

    // epilogue
    int gm0 = mbase + warp_m*32 + (lane >> 2);
    int gnb = nbase + warp_n*64 + (lane & 3) * 2;
    #pragma unroll
    for (int mt = 0; mt < 2; mt++) {
        #pragma unroll
        for (int half = 0; half < 2; half++) {
            int gm = gm0 + mt*16 + half*8;
            size_t rN = (size_t)gm * N;
            #pragma unroll
            for (int nt = 0; nt < 8; nt++) {
                int gn = gnb + nt*8;
                float v0 = acc[mt][nt][half*2]     + bias[gn];
                float v1 = acc[mt][nt][half*2 + 1] + bias[gn + 1];
                if (mode == 1) {
                    v0 = 0.5f * v0 * (1.0f + erff(v0 * 0.70710678118654752440f));
                    v1 = 0.5f * v1 * (1.0f + erff(v1 * 0.70710678118654752440f));
                    __nv_bfloat16 h0 = __float2bfloat16(v0), h1 = __float2bfloat16(v1);
                    __nv_bfloat162 ph, pl;
                    ph.x = h0; ph.y = h1;
                    pl.x = __float2bfloat16(v0 - __bfloat162float(h0));
                    pl.y = __float2bfloat16(v1 - __bfloat162float(h1));
                    *(__nv_bfloat162*)(Oh + rN + gn) = ph;
                    *(__nv_bfloat162*)(Ol + rN + gn) = pl;
                } else {
                    if (mode == 2) {
                        float2 ad = *(const float2*)(addend + rN + gn);
                        v0 += ad.x; v1 += ad.y;
                    }
                    float2 o; o.x = v0; o.y = v1;
                    *(float2*)(C + rN + gn) = o;
                }
            }
        }
    }
}

// ===================== flash attention ======================================
// 64 q-rows per block, K/V tiles of 64 rows in SMEM, online softmax.
// 256 threads: thread = (q-row qr = tid>>2, quad-slot s = tid&3 owning dims
// [16s,16s+16)). Output written as bf16 (hi,lo) split directly.
__global__ __launch_bounds__(256, 2) void flash_attn(
        const float* __restrict__ qkv,
        __nv_bfloat16* __restrict__ aoh, __nv_bfloat16* __restrict__ aol) {
    __shared__ float Ks[64*64];
    __shared__ float Vs[64*64];
    int qt = blockIdx.x, hh = blockIdx.y, b = blockIdx.z;
    int tid = threadIdx.x;
    int qr = tid >> 2, d0 = (tid & 3) * 16;
    int grow = b*SS + qt*64 + qr;
    const float* qp = qkv + (size_t)grow * 3072 + hh*HD + d0;
    float q[16], o[16];
    #pragma unroll
    for (int i = 0; i < 16; i += 4) {
        float4 t = *(const float4*)(qp + i);
        q[i]   = t.x * 0.125f; q[i+1] = t.y * 0.125f;
        q[i+2] = t.z * 0.125f; q[i+3] = t.w * 0.125f;
        o[i] = o[i+1] = o[i+2] = o[i+3] = 0.f;
    }
    float m = -1e30f, l = 0.f;
    int lj = tid >> 2, lc = (tid & 3) * 16;
    const float* kb0 = qkv + (size_t)(b*SS) * 3072 + DD + hh*HD;

    for (int kt = 0; kt <= qt; kt++) {
        __syncthreads();
        const float* kg = kb0 + (size_t)(kt*64 + lj) * 3072 + lc;
        #pragma unroll
        for (int i = 0; i < 16; i += 4) {
            *(float4*)(Ks + lj*64 + lc + i) = *(const float4*)(kg + i);
            *(float4*)(Vs + lj*64 + lc + i) = *(const float4*)(kg + DD + i);
        }
        __syncthreads();
        int jmax = (kt == qt) ? qr : 63;
        #pragma unroll
        for (int half = 0; half < 2; half++) {
            float sc[32];
            #pragma unroll
            for (int j = 0; j < 32; j++) {
                const float* kr = Ks + (half*32 + j)*64 + d0;
                float s = 0.f;
                #pragma unroll
                for (int i = 0; i < 16; i += 4) {
                    float4 kv = *(const float4*)(kr + i);
                    s += kv.x*q[i] + kv.y*q[i+1] + kv.z*q[i+2] + kv.w*q[i+3];
                }
                sc[j] = s;
            }
            #pragma unroll
            for (int j = 0; j < 32; j++) {
                sc[j] += __shfl_xor_sync(0xffffffffu, sc[j], 1);
                sc[j] += __shfl_xor_sync(0xffffffffu, sc[j], 2);
            }
            float tm = m;
            #pragma unroll
            for (int j = 0; j < 32; j++) {
                if (half*32 + j > jmax) sc[j] = -1e30f;
                tm = fmaxf(tm, sc[j]);
            }
            float alpha = __expf(m - tm);
            m = tm;
            float ps = 0.f;
            #pragma unroll
            for (int j = 0; j < 32; j++) { sc[j] = __expf(sc[j] - m); ps += sc[j]; }
            l = l * alpha + ps;
            #pragma unroll
            for (int i = 0; i < 16; i++) o[i] *= alpha;
            #pragma unroll
            for (int j = 0; j < 32; j++) {
                const float* vr = Vs + (half*32 + j)*64 + d0;
                float p = sc[j];
                #pragma unroll
                for (int i = 0; i < 16; i += 4) {
                    float4 vv = *(const float4*)(vr + i);
                    o[i]   += p * vv.x; o[i+1] += p * vv.y;
                    o[i+2] += p * vv.z; o[i+3] += p * vv.w;
                }
            }
        }
    }
    float inv = 1.0f / l;
    size_t ob = (size_t)grow * DD + hh*HD + d0;
    #pragma unroll
    for (int i = 0; i < 16; i += 2) {
        float v0 = o[i] * inv, v1 = o[i+1] * inv;
        __nv_bfloat16 h0 = __float2bfloat16(v0), h1 = __float2bfloat16(v1);
        __nv_bfloat162 ph, pl;
        ph.x = h0; ph.y = h1;
        pl.x = __float2bfloat16(v0 - __bfloat162float(h0));
        pl.y = __float2bfloat16(v1 - __bfloat162float(h1));
        *(__nv_bfloat162*)(aoh + ob + i) = ph;
        *(__nv_bfloat162*)(aol + ob + i) = pl;
    }
}

// ===================== host =====================
extern "C" void kernel_launch(void* const* d_in, const int* in_sizes, int n_in,
                              void* d_out, int out_size) {
    const void*  x     = d_in[0];
    const float* tok   = (const float*)d_in[1];
    const float* pos   = (const float*)d_in[2];
    const float* Wq    = (const float*)d_in[3];
    const float* bq    = (const float*)d_in[4];
    const float* Wk    = (const float*)d_in[5];
    const float* bk    = (const float*)d_in[6];
    const float* Wv    = (const float*)d_in[7];
    const float* bv    = (const float*)d_in[8];
    const float* Wo    = (const float*)d_in[9];
    const float* bo    = (const float*)d_in[10];
    const float* ln1g  = (const float*)d_in[11];
    const float* ln1b  = (const float*)d_in[12];
    const float* ln2g  = (const float*)d_in[13];
    const float* ln2b  = (const float*)d_in[14];
    const float* W1    = (const float*)d_in[15];
    const float* b1    = (const float*)d_in[16];
    const float* W2    = (const float*)d_in[17];
    const float* b2    = (const float*)d_in[18];
    const float* lnfg  = (const float*)d_in[19];
    const float* lnfb  = (const float*)d_in[20];
    const float* Wout  = (const float*)d_in[21];
    const float* bout  = (const float*)d_in[22];
    float* out = (float*)d_out;

    cudaFuncSetAttribute(gemm_hmma3, cudaFuncAttributeMaxDynamicSharedMemorySize, GEMM_SMEM);

    float *h, *qkv, *bqkv;
    __nv_bfloat16 *ainh, *ainl, *aoh, *aol, *ffnh, *ffnl;
    __nv_bfloat16 *wqkvh, *wqkvl, *woh, *wol, *w1h, *w1l, *w2h, *w2l, *wouth, *woutl;
    cudaGetSymbolAddress((void**)&h,    g_h);
    cudaGetSymbolAddress((void**)&qkv,  g_qkv);
    cudaGetSymbolAddress((void**)&bqkv, g_bqkv);
    cudaGetSymbolAddress((void**)&ainh, g_ainh); cudaGetSymbolAddress((void**)&ainl, g_ainl);
    cudaGetSymbolAddress((void**)&aoh,  g_aoh);  cudaGetSymbolAddress((void**)&aol,  g_aol);
    cudaGetSymbolAddress((void**)&ffnh, g_ffnh); cudaGetSymbolAddress((void**)&ffnl, g_ffnl);
    cudaGetSymbolAddress((void**)&wqkvh, g_wqkvh); cudaGetSymbolAddress((void**)&wqkvl, g_wqkvl);
    cudaGetSymbolAddress((void**)&woh,  g_woh);  cudaGetSymbolAddress((void**)&wol,  g_wol);
    cudaGetSymbolAddress((void**)&w1h,  g_w1h);  cudaGetSymbolAddress((void**)&w1l,  g_w1l);
    cudaGetSymbolAddress((void**)&w2h,  g_w2h);  cudaGetSymbolAddress((void**)&w2l,  g_w2l);
    cudaGetSymbolAddress((void**)&wouth, g_wouth); cudaGetSymbolAddress((void**)&woutl, g_woutl);

    detect_kernel<<<1, 256>>>((const int*)x);
    embed_kernel<<<MROWS, 256>>>(x, tok, pos, h);

    // ---- weight prep: transpose + bf16 split ----
    dim3 tb(32, 8);
    size_t dd = (size_t)DD*DD, df = (size_t)DD*FF;
    tsplit<<<dim3(DD/32, DD/32, LL), tb>>>(Wq, wqkvh,        wqkvl,        DD, DD, dd, 3*dd);
    tsplit<<<dim3(DD/32, DD/32, LL), tb>>>(Wk, wqkvh + dd,   wqkvl + dd,   DD, DD, dd, 3*dd);
    tsplit<<<dim3(DD/32, DD/32, LL), tb>>>(Wv, wqkvh + 2*dd, wqkvl + 2*dd, DD, DD, dd, 3*dd);
    tsplit<<<dim3(DD/32, DD/32, LL), tb>>>(Wo, woh, wol, DD, DD, dd, dd);
    tsplit<<<dim3(FF/32, DD/32, LL), tb>>>(W1, w1h, w1l, DD, FF, df, df);
    tsplit<<<dim3(DD/32, FF/32, LL), tb>>>(W2, w2h, w2l, FF, DD, df, df);
    tsplit<<<dim3(VV/32, DD/32, 1),  tb>>>(Wout, wouth, woutl, DD, VV, 0, 0);
    packb<<<LL, DD>>>(bq, bk, bv, bqkv);

    dim3 gAtt(SS/64, HH, BB);

    for (int i = 0; i < LL; i++) {
        size_t w3 = (size_t)i * 3 * dd;
        layernorm_split<<<MROWS, 256>>>(h, ln1g + i*DD, ln1b + i*DD, ainh, ainl);
        gemm_hmma3<<<dim3(24, 8), 512, GEMM_SMEM>>>(
            ainh, ainl, wqkvh + w3, wqkvl + w3, bqkv + i*3*DD,
            nullptr, qkv, nullptr, nullptr, 3*DD, DD, 0);
        flash_attn<<<gAtt, 256>>>(qkv, aoh, aol);
        gemm_hmma3<<<dim3(8, 8), 512, GEMM_SMEM>>>(
            aoh, aol, woh + i*dd, wol + i*dd, bo + i*DD,
            h, h, nullptr, nullptr, DD, DD, 2);
        layernorm_split<<<MROWS, 256>>>(h, ln2g + i*DD, ln2b + i*DD, ainh, ainl);
        gemm_hmma3<<<dim3(32, 8), 512, GEMM_SMEM>>>(
            ainh, ainl, w1h + i*df, w1l + i*df, b1 + i*FF,
            nullptr, nullptr, ffnh, ffnl, FF, DD, 1);
        gemm_hmma3<<<dim3(8, 8), 512, GEMM_SMEM>>>(
            ffnh, ffnl, w2h + i*df, w2l + i*df, b2 + i*DD,
            h, h, nullptr, nullptr, DD, FF, 2);
    }
    layernorm_split<<<MROWS, 256>>>(h, lnfg, lnfb, ainh, ainl);
    gemm_hmma3<<<dim3(VV/128, 8), 512, GEMM_SMEM>>>(
        ainh, ainl, wouth, woutl, bout,
        nullptr, out, nullptr, nullptr, VV, DD, 0);
}

// round 16
// speedup vs baseline: 1.1473x; 1.1473x over previous
#include <cuda_runtime.h>
#include <cuda_bf16.h>
#include <math.h>
#include <stdint.h>

// Problem dims
#define BB 2
#define SS 1024
#define DD 1024
#define HH 16
#define HD 64
#define LL 3
#define FF 4096
#define VV 32000
#define MROWS (BB*SS)   // 2048

// ===================== PTX helpers (sm_80-class only: ldmatrix/mma/cp.async) ==
__device__ __forceinline__ uint32_t smem_u32(const void* p) {
    uint32_t a;
    asm("{ .reg .u64 t; cvta.to.shared.u64 t, %1; cvt.u32.u64 %0, t; }" : "=r"(a) : "l"(p));
    return a;
}
__device__ __forceinline__ void ldsm_x4(uint32_t& r0, uint32_t& r1, uint32_t& r2, uint32_t& r3, uint32_t addr) {
    asm volatile("ldmatrix.sync.aligned.m8n8.x4.shared.b16 {%0,%1,%2,%3}, [%4];"
        : "=r"(r0), "=r"(r1), "=r"(r2), "=r"(r3) : "r"(addr));
}
__device__ __forceinline__ void mma_bf16(float* d, const uint32_t* a, const uint32_t* b) {
    asm volatile("mma.sync.aligned.m16n8k16.row.col.f32.bf16.bf16.f32 "
        "{%0,%1,%2,%3}, {%4,%5,%6,%7}, {%8,%9}, {%0,%1,%2,%3};"
        : "+f"(d[0]), "+f"(d[1]), "+f"(d[2]), "+f"(d[3])
        : "r"(a[0]), "r"(a[1]), "r"(a[2]), "r"(a[3]), "r"(b[0]), "r"(b[1]));
}
__device__ __forceinline__ void cp_async16(uint32_t saddr, const void* gaddr) {
    asm volatile("cp.async.cg.shared.global [%0], [%1], 16;" :: "r"(saddr), "l"(gaddr));
}
#define CP_COMMIT() asm volatile("cp.async.commit_group;" ::: "memory")
#define CP_WAIT1()  asm volatile("cp.async.wait_group 1;" ::: "memory")
#define CP_WAIT0()  asm volatile("cp.async.wait_group 0;" ::: "memory")

// ===================== device scratch (no allocations) =====================
__device__ float g_h  [MROWS*DD];
__device__ float g_qkv[MROWS*3*DD];
__device__ float g_bqkv[LL*3*DD];
__device__ int   g_is64;

__device__ __nv_bfloat16 g_ainh[MROWS*DD], g_ainl[MROWS*DD];
__device__ __nv_bfloat16 g_aoh [MROWS*DD], g_aol [MROWS*DD];
__device__ __nv_bfloat16 g_ffnh[MROWS*FF], g_ffnl[MROWS*FF];

__device__ __nv_bfloat16 g_wqkvh[LL*3*DD*DD], g_wqkvl[LL*3*DD*DD];
__device__ __nv_bfloat16 g_woh [LL*DD*DD],   g_wol [LL*DD*DD];
__device__ __nv_bfloat16 g_w1h [LL*FF*DD],   g_w1l [LL*FF*DD];   // [F,D] per layer
__device__ __nv_bfloat16 g_w2h [LL*DD*FF],   g_w2l [LL*DD*FF];   // [D,F] per layer
__device__ __nv_bfloat16 g_wouth[(size_t)VV*DD], g_woutl[(size_t)VV*DD];

// ===================== small kernels =====================
__global__ void detect_kernel(const int* __restrict__ xw) {
    __shared__ int nz;
    if (threadIdx.x == 0) nz = 0;
    __syncthreads();
    int local = 0;
    for (int i = threadIdx.x; i < 1024; i += blockDim.x)
        if (xw[2*i + 1] != 0) local++;
    if (local) atomicAdd(&nz, local);
    __syncthreads();
    if (threadIdx.x == 0) g_is64 = (nz == 0) ? 1 : 0;
}

__global__ void embed_kernel(const void* __restrict__ x,
                             const float* __restrict__ tok,
                             const float* __restrict__ pos,
                             float* __restrict__ h) {
    int bs = blockIdx.x;
    int s  = bs & (SS - 1);
    long long tokid = g_is64 ? ((const long long*)x)[bs]
                             : (long long)((const int*)x)[bs];
    const float4* tr = (const float4*)(tok + (size_t)tokid * DD);
    const float4* pr = (const float4*)(pos + (size_t)s * DD);
    float4*       hr = (float4*)(h + (size_t)bs * DD);
    for (int i = threadIdx.x; i < DD/4; i += blockDim.x) {
        float4 t = tr[i], p = pr[i];
        hr[i] = make_float4(t.x+p.x, t.y+p.y, t.z+p.z, t.w+p.w);
    }
}

// LayerNorm fused with bf16 (hi,lo) split output
__global__ __launch_bounds__(256) void layernorm_split(
        const float* __restrict__ x, const float* __restrict__ g,
        const float* __restrict__ b,
        __nv_bfloat16* __restrict__ yh, __nv_bfloat16* __restrict__ yl) {
    __shared__ float s1[256], s2[256];
    int row = blockIdx.x, tid = threadIdx.x;
    const float4* xr = (const float4*)(x + (size_t)row * DD);
    float4 v = xr[tid];
    float sum = v.x + v.y + v.z + v.w;
    float sq  = v.x*v.x + v.y*v.y + v.z*v.z + v.w*v.w;
    s1[tid] = sum; s2[tid] = sq;
    __syncthreads();
    for (int off = 128; off > 0; off >>= 1) {
        if (tid < off) { s1[tid] += s1[tid+off]; s2[tid] += s2[tid+off]; }
        __syncthreads();
    }
    float mean = s1[0] * (1.0f/DD);
    float var  = s2[0] * (1.0f/DD) - mean*mean;
    float rstd = rsqrtf(var + 1e-5f);
    float4 gg = ((const float4*)g)[tid], bb = ((const float4*)b)[tid];
    float o0 = (v.x-mean)*rstd*gg.x + bb.x;
    float o1 = (v.y-mean)*rstd*gg.y + bb.y;
    float o2 = (v.z-mean)*rstd*gg.z + bb.z;
    float o3 = (v.w-mean)*rstd*gg.w + bb.w;
    __nv_bfloat16 h0 = __float2bfloat16(o0), h1 = __float2bfloat16(o1);
    __nv_bfloat16 h2 = __float2bfloat16(o2), h3 = __float2bfloat16(o3);
    __nv_bfloat162 p0, p1, q0, q1;
    p0.x = h0; p0.y = h1; p1.x = h2; p1.y = h3;
    q0.x = __float2bfloat16(o0 - __bfloat162float(h0));
    q0.y = __float2bfloat16(o1 - __bfloat162float(h1));
    q1.x = __float2bfloat16(o2 - __bfloat162float(h2));
    q1.y = __float2bfloat16(o3 - __bfloat162float(h3));
    size_t base2 = (size_t)row * (DD/2) + tid*2;
    ((__nv_bfloat162*)yh)[base2]   = p0;
    ((__nv_bfloat162*)yh)[base2+1] = p1;
    ((__nv_bfloat162*)yl)[base2]   = q0;
    ((__nv_bfloat162*)yl)[base2+1] = q1;
}

// transpose + split: in [K,N] fp32 (layer-strided) -> out [N,K] bf16 hi/lo
__global__ __launch_bounds__(256) void tsplit(
        const float* __restrict__ in, __nv_bfloat16* __restrict__ oh,
        __nv_bfloat16* __restrict__ ol, int K, int N,
        size_t inLS, size_t outLS) {
    __shared__ float t[32][33];
    int z = blockIdx.z;
    in += (size_t)z * inLS; oh += (size_t)z * outLS; ol += (size_t)z * outLS;
    int nb = blockIdx.x * 32, kb = blockIdx.y * 32;
    int tx = threadIdx.x, ty = threadIdx.y;   // 32 x 8
    #pragma unroll
    for (int r = 0; r < 32; r += 8)
        t[ty+r][tx] = in[(size_t)(kb+ty+r) * N + nb + tx];
    __syncthreads();
    #pragma unroll
    for (int r = 0; r < 32; r += 8) {
        float a = t[tx][ty+r];
        __nv_bfloat16 h = __float2bfloat16(a);
        float lo = a - __bfloat162float(h);
        size_t o = (size_t)(nb+ty+r) * K + kb + tx;
        oh[o] = h; ol[o] = __float2bfloat16(lo);
    }
}

__global__ void packb(const float* __restrict__ bq, const float* __restrict__ bk,
                      const float* __restrict__ bv, float* __restrict__ out) {
    int l = blockIdx.x, t = threadIdx.x;
    out[l*3*DD + t]        = bq[l*DD + t];
    out[l*3*DD + DD + t]   = bk[l*DD + t];
    out[l*3*DD + 2*DD + t] = bv[l*DD + t];
}

// ===================== HMMA bf16x3 GEMM (mma.sync m16n8k16) ==================
// C[M,N] = A @ B^T.  A = Ah+Al [M,K] bf16 row-major; B^T = Bh+Bl [N,K] bf16.
// Block tile 128x128, BK=32, 256 threads = 8 warps (4M x 2N), warp tile 32x64.
// 2-stage cp.async pipeline, 80KB smem -> 2 CTAs/SM (latency hiding across
// independent CTAs). Inner loop keeps B fragments per-p to fit the 128-reg cap.
// mode 0: C = acc + bias
// mode 1: g = gelu(acc+bias); Oh/Ol = bf16 split(g)
// mode 2: C = acc + bias + addend
#define STG_A_H 0
#define STG_A_L 10240
#define STG_B_H 20480
#define STG_B_L 30720
#define STG_SZ  40960
#define GEMM_SMEM (2*STG_SZ)

__global__ __launch_bounds__(256, 2) void gemm_hmma3(
        const __nv_bfloat16* __restrict__ Ah, const __nv_bfloat16* __restrict__ Al,
        const __nv_bfloat16* __restrict__ Bh, const __nv_bfloat16* __restrict__ Bl,
        const float* __restrict__ bias, const float* __restrict__ addend,
        float* __restrict__ C, __nv_bfloat16* __restrict__ Oh, __nv_bfloat16* __restrict__ Ol,
        int N, int K, int mode) {
    extern __shared__ char smem[];
    uint32_t sb = smem_u32(smem);
    int tid = threadIdx.x, wid = tid >> 5, lane = tid & 31;
    int warp_m = wid & 3, warp_n = wid >> 2;
    int nbase = blockIdx.x * 128, mbase = blockIdx.y * 128;

    const char* Agh = (const char*)(Ah + (size_t)mbase * K);
    const char* Agl = (const char*)(Al + (size_t)mbase * K);
    const char* Bgh = (const char*)(Bh + (size_t)nbase * K);
    const char* Bgl = (const char*)(Bl + (size_t)nbase * K);
    size_t K2 = (size_t)K * 2;

    // per-thread load slots: 2 x 16B chunks per array per stage
    int r0 = tid >> 2,            c0 = (tid & 3) * 16;
    int r1 = (tid + 256) >> 2,    c1 = ((tid + 256) & 3) * 16;
    uint32_t so0 = (uint32_t)r0 * 80 + c0;
    uint32_t so1 = (uint32_t)r1 * 80 + c1;

    float acc[2][8][4];
    #pragma unroll
    for (int i = 0; i < 2; i++)
        #pragma unroll
        for (int j = 0; j < 8; j++)
            #pragma unroll
            for (int q = 0; q < 4; q++) acc[i][j][q] = 0.f;

    int nk = K >> 5;

    // prologue: stage 0
    {
        size_t g0 = (size_t)r0 * K2 + c0;
        size_t g1 = (size_t)r1 * K2 + c1;
        cp_async16(sb + STG_A_H + so0, Agh + g0); cp_async16(sb + STG_A_H + so1, Agh + g1);
        cp_async16(sb + STG_A_L + so0, Agl + g0); cp_async16(sb + STG_A_L + so1, Agl + g1);
        cp_async16(sb + STG_B_H + so0, Bgh + g0); cp_async16(sb + STG_B_H + so1, Bgh + g1);
        cp_async16(sb + STG_B_L + so0, Bgl + g0); cp_async16(sb + STG_B_L + so1, Bgl + g1);
    }
    CP_COMMIT();

    for (int c = 0; c < nk; c++) {
        if (c + 1 < nk) {
            uint32_t st = ((c + 1) & 1) * STG_SZ;
            size_t kb = (size_t)(c + 1) * 64;
            size_t g0 = (size_t)r0 * K2 + kb + c0;
            size_t g1 = (size_t)r1 * K2 + kb + c1;
            cp_async16(sb + st + STG_A_H + so0, Agh + g0); cp_async16(sb + st + STG_A_H + so1, Agh + g1);
            cp_async16(sb + st + STG_A_L + so0, Agl + g0); cp_async16(sb + st + STG_A_L + so1, Agl + g1);
            cp_async16(sb + st + STG_B_H + so0, Bgh + g0); cp_async16(sb + st + STG_B_H + so1, Bgh + g1);
            cp_async16(sb + st + STG_B_L + so0, Bgl + g0); cp_async16(sb + st + STG_B_L + so1, Bgl + g1);
        }
        CP_COMMIT();
        CP_WAIT1();
        __syncthreads();

        uint32_t base = sb + (c & 1) * STG_SZ;
        #pragma unroll
        for (int ks = 0; ks < 2; ks++) {
            uint32_t ah[2][4], al[2][4];
            #pragma unroll
            for (int mt = 0; mt < 2; mt++) {
                uint32_t ra = base + (uint32_t)(warp_m*32 + mt*16 + (lane & 15)) * 80
                            + (uint32_t)ks*32 + (uint32_t)(lane >> 4) * 16;
                ldsm_x4(ah[mt][0], ah[mt][1], ah[mt][2], ah[mt][3], ra + STG_A_H);
                ldsm_x4(al[mt][0], al[mt][1], al[mt][2], al[mt][3], ra + STG_A_L);
            }
            #pragma unroll
            for (int p = 0; p < 4; p++) {
                uint32_t rbad = base + (uint32_t)(warp_n*64 + p*16 + ((lane >> 4) * 8) + (lane & 7)) * 80
                              + (uint32_t)((lane >> 3) & 1) * 16 + (uint32_t)ks*32;
                uint32_t bh[2][2], bl[2][2];
                uint32_t x0, x1, x2, x3;
                ldsm_x4(x0, x1, x2, x3, rbad + STG_B_H);
                bh[0][0] = x0; bh[0][1] = x1; bh[1][0] = x2; bh[1][1] = x3;
                ldsm_x4(x0, x1, x2, x3, rbad + STG_B_L);
                bl[0][0] = x0; bl[0][1] = x1; bl[1][0] = x2; bl[1][1] = x3;
                #pragma unroll
                for (int mt = 0; mt < 2; mt++)
                    #pragma unroll
                    for (int q = 0; q < 2; q++) {
                        mma_bf16(acc[mt][p*2+q], ah[mt], bh[q]);
                        mma_bf16(acc[mt][p*2+q], ah[mt], bl[q]);
                        mma_bf16(acc[mt][p*2+q], al[mt], bh[q]);
                    }
            }
        }
        __syncthreads();
    }
    CP_WAIT0();

    // epilogue
    int gm0 = mbase + warp_m*32 + (lane >> 2);
    int gnb = nbase + warp_n*64 + (lane & 3) * 2;
    #pragma unroll
    for (int mt = 0; mt < 2; mt++) {
        #pragma unroll
        for (int half = 0; half < 2; half++) {
            int gm = gm0 + mt*16 + half*8;
            size_t rN = (size_t)gm * N;
            #pragma unroll
            for (int nt = 0; nt < 8; nt++) {
                int gn = gnb + nt*8;
                float v0 = acc[mt][nt][half*2]     + bias[gn];
                float v1 = acc[mt][nt][half*2 + 1] + bias[gn + 1];
                if (mode == 1) {
                    v0 = 0.5f * v0 * (1.0f + erff(v0 * 0.70710678118654752440f));
                    v1 = 0.5f * v1 * (1.0f + erff(v1 * 0.70710678118654752440f));
                    __nv_bfloat16 h0 = __float2bfloat16(v0), h1 = __float2bfloat16(v1);
                    __nv_bfloat162 ph, pl;
                    ph.x = h0; ph.y = h1;
                    pl.x = __float2bfloat16(v0 - __bfloat162float(h0));
                    pl.y = __float2bfloat16(v1 - __bfloat162float(h1));
                    *(__nv_bfloat162*)(Oh + rN + gn) = ph;
                    *(__nv_bfloat162*)(Ol + rN + gn) = pl;
                } else {
                    if (mode == 2) {
                        float2 ad = *(const float2*)(addend + rN + gn);
                        v0 += ad.x; v1 += ad.y;
                    }
                    float2 o; o.x = v0; o.y = v1;
                    *(float2*)(C + rN + gn) = o;
                }
            }
        }
    }
}

// ===================== flash attention ======================================
// 64 q-rows per block, K/V tiles of 64 rows in SMEM, online softmax.
// 256 threads: thread = (q-row qr = tid>>2, quad-slot s = tid&3 owning dims
// [16s,16s+16)). Output written as bf16 (hi,lo) split directly.
// q-tiles are processed longest-first (qt reversed) to shrink the tail wave.
__global__ __launch_bounds__(256, 2) void flash_attn(
        const float* __restrict__ qkv,
        __nv_bfloat16* __restrict__ aoh, __nv_bfloat16* __restrict__ aol) {
    __shared__ float Ks[64*64];
    __shared__ float Vs[64*64];
    int qt = (int)gridDim.x - 1 - (int)blockIdx.x;  // longest work first
    int hh = blockIdx.y, b = blockIdx.z;
    int tid = threadIdx.x;
    int qr = tid >> 2, d0 = (tid & 3) * 16;
    int grow = b*SS + qt*64 + qr;
    const float* qp = qkv + (size_t)grow * 3072 + hh*HD + d0;
    float q[16], o[16];
    #pragma unroll
    for (int i = 0; i < 16; i += 4) {
        float4 t = *(const float4*)(qp + i);
        q[i]   = t.x * 0.125f; q[i+1] = t.y * 0.125f;
        q[i+2] = t.z * 0.125f; q[i+3] = t.w * 0.125f;
        o[i] = o[i+1] = o[i+2] = o[i+3] = 0.f;
    }
    float m = -1e30f, l = 0.f;
    int lj = tid >> 2, lc = (tid & 3) * 16;
    const float* kb0 = qkv + (size_t)(b*SS) * 3072 + DD + hh*HD;

    for (int kt = 0; kt <= qt; kt++) {
        __syncthreads();
        const float* kg = kb0 + (size_t)(kt*64 + lj) * 3072 + lc;
        #pragma unroll
        for (int i = 0; i < 16; i += 4) {
            *(float4*)(Ks + lj*64 + lc + i) = *(const float4*)(kg + i);
            *(float4*)(Vs + lj*64 + lc + i) = *(const float4*)(kg + DD + i);
        }
        __syncthreads();
        int jmax = (kt == qt) ? qr : 63;
        #pragma unroll
        for (int half = 0; half < 2; half++) {
            float sc[32];
            #pragma unroll
            for (int j = 0; j < 32; j++) {
                const float* kr = Ks + (half*32 + j)*64 + d0;
                float s = 0.f;
                #pragma unroll
                for (int i = 0; i < 16; i += 4) {
                    float4 kv = *(const float4*)(kr + i);
                    s += kv.x*q[i] + kv.y*q[i+1] + kv.z*q[i+2] + kv.w*q[i+3];
                }
                sc[j] = s;
            }
            #pragma unroll
            for (int j = 0; j < 32; j++) {
                sc[j] += __shfl_xor_sync(0xffffffffu, sc[j], 1);
                sc[j] += __shfl_xor_sync(0xffffffffu, sc[j], 2);
            }
            float tm = m;
            #pragma unroll
            for (int j = 0; j < 32; j++) {
                if (half*32 + j > jmax) sc[j] = -1e30f;
                tm = fmaxf(tm, sc[j]);
            }
            float alpha = __expf(m - tm);
            m = tm;
            float ps = 0.f;
            #pragma unroll
            for (int j = 0; j < 32; j++) { sc[j] = __expf(sc[j] - m); ps += sc[j]; }
            l = l * alpha + ps;
            #pragma unroll
            for (int i = 0; i < 16; i++) o[i] *= alpha;
            #pragma unroll
            for (int j = 0; j < 32; j++) {
                const float* vr = Vs + (half*32 + j)*64 + d0;
                float p = sc[j];
                #pragma unroll
                for (int i = 0; i < 16; i += 4) {
                    float4 vv = *(const float4*)(vr + i);
                    o[i]   += p * vv.x; o[i+1] += p * vv.y;
                    o[i+2] += p * vv.z; o[i+3] += p * vv.w;
                }
            }
        }
    }
    float inv = 1.0f / l;
    size_t ob = (size_t)grow * DD + hh*HD + d0;
    #pragma unroll
    for (int i = 0; i < 16; i += 2) {
        float v0 = o[i] * inv, v1 = o[i+1] * inv;
        __nv_bfloat16 h0 = __float2bfloat16(v0), h1 = __float2bfloat16(v1);
        __nv_bfloat162 ph, pl;
        ph.x = h0; ph.y = h1;
        pl.x = __float2bfloat16(v0 - __bfloat162float(h0));
        pl.y = __float2bfloat16(v1 - __bfloat162float(h1));
        *(__nv_bfloat162*)(aoh + ob + i) = ph;
        *(__nv_bfloat162*)(aol + ob + i) = pl;
    }
}

// ===================== host =====================
extern "C" void kernel_launch(void* const* d_in, const int* in_sizes, int n_in,
                              void* d_out, int out_size) {
    const void*  x     = d_in[0];
    const float* tok   = (const float*)d_in[1];
    const float* pos   = (const float*)d_in[2];
    const float* Wq    = (const float*)d_in[3];
    const float* bq    = (const float*)d_in[4];
    const float* Wk    = (const float*)d_in[5];
    const float* bk    = (const float*)d_in[6];
    const float* Wv    = (const float*)d_in[7];
    const float* bv    = (const float*)d_in[8];
    const float* Wo    = (const float*)d_in[9];
    const float* bo    = (const float*)d_in[10];
    const float* ln1g  = (const float*)d_in[11];
    const float* ln1b  = (const float*)d_in[12];
    const float* ln2g  = (const float*)d_in[13];
    const float* ln2b  = (const float*)d_in[14];
    const float* W1    = (const float*)d_in[15];
    const float* b1    = (const float*)d_in[16];
    const float* W2    = (const float*)d_in[17];
    const float* b2    = (const float*)d_in[18];
    const float* lnfg  = (const float*)d_in[19];
    const float* lnfb  = (const float*)d_in[20];
    const float* Wout  = (const float*)d_in[21];
    const float* bout  = (const float*)d_in[22];
    float* out = (float*)d_out;

    cudaFuncSetAttribute(gemm_hmma3, cudaFuncAttributeMaxDynamicSharedMemorySize, GEMM_SMEM);

    float *h, *qkv, *bqkv;
    __nv_bfloat16 *ainh, *ainl, *aoh, *aol, *ffnh, *ffnl;
    __nv_bfloat16 *wqkvh, *wqkvl, *woh, *wol, *w1h, *w1l, *w2h, *w2l, *wouth, *woutl;
    cudaGetSymbolAddress((void**)&h,    g_h);
    cudaGetSymbolAddress((void**)&qkv,  g_qkv);
    cudaGetSymbolAddress((void**)&bqkv, g_bqkv);
    cudaGetSymbolAddress((void**)&ainh, g_ainh); cudaGetSymbolAddress((void**)&ainl, g_ainl);
    cudaGetSymbolAddress((void**)&aoh,  g_aoh);  cudaGetSymbolAddress((void**)&aol,  g_aol);
    cudaGetSymbolAddress((void**)&ffnh, g_ffnh); cudaGetSymbolAddress((void**)&ffnl, g_ffnl);
    cudaGetSymbolAddress((void**)&wqkvh, g_wqkvh); cudaGetSymbolAddress((void**)&wqkvl, g_wqkvl);
    cudaGetSymbolAddress((void**)&woh,  g_woh);  cudaGetSymbolAddress((void**)&wol,  g_wol);
    cudaGetSymbolAddress((void**)&w1h,  g_w1h);  cudaGetSymbolAddress((void**)&w1l,  g_w1l);
    cudaGetSymbolAddress((void**)&w2h,  g_w2h);  cudaGetSymbolAddress((void**)&w2l,  g_w2l);
    cudaGetSymbolAddress((void**)&wouth, g_wouth); cudaGetSymbolAddress((void**)&woutl, g_woutl);

    detect_kernel<<<1, 256>>>((const int*)x);
    embed_kernel<<<MROWS, 256>>>(x, tok, pos, h);

    // ---- weight prep: transpose + bf16 split ----
    dim3 tb(32, 8);
    size_t dd = (size_t)DD*DD, df = (size_t)DD*FF;
    tsplit<<<dim3(DD/32, DD/32, LL), tb>>>(Wq, wqkvh,        wqkvl,        DD, DD, dd, 3*dd);
    tsplit<<<dim3(DD/32, DD/32, LL), tb>>>(Wk, wqkvh + dd,   wqkvl + dd,   DD, DD, dd, 3*dd);
    tsplit<<<dim3(DD/32, DD/32, LL), tb>>>(Wv, wqkvh + 2*dd, wqkvl + 2*dd, DD, DD, dd, 3*dd);
    tsplit<<<dim3(DD/32, DD/32, LL), tb>>>(Wo, woh, wol, DD, DD, dd, dd);
    tsplit<<<dim3(FF/32, DD/32, LL), tb>>>(W1, w1h, w1l, DD, FF, df, df);
    tsplit<<<dim3(DD/32, FF/32, LL), tb>>>(W2, w2h, w2l, FF, DD, df, df);
    tsplit<<<dim3(VV/32, DD/32, 1),  tb>>>(Wout, wouth, woutl, DD, VV, 0, 0);
    packb<<<LL, DD>>>(bq, bk, bv, bqkv);

    dim3 gAtt(SS/64, HH, BB);

    for (int i = 0; i < LL; i++) {
        size_t w3 = (size_t)i * 3 * dd;
        layernorm_split<<<MROWS, 256>>>(h, ln1g + i*DD, ln1b + i*DD, ainh, ainl);
        gemm_hmma3<<<dim3(24, 16), 256, GEMM_SMEM>>>(
            ainh, ainl, wqkvh + w3, wqkvl + w3, bqkv + i*3*DD,
            nullptr, qkv, nullptr, nullptr, 3*DD, DD, 0);
        flash_attn<<<gAtt, 256>>>(qkv, aoh, aol);
        gemm_hmma3<<<dim3(8, 16), 256, GEMM_SMEM>>>(
            aoh, aol, woh + i*dd, wol + i*dd, bo + i*DD,
            h, h, nullptr, nullptr, DD, DD, 2);
        layernorm_split<<<MROWS, 256>>>(h, ln2g + i*DD, ln2b + i*DD, ainh, ainl);
        gemm_hmma3<<<dim3(32, 16), 256, GEMM_SMEM>>>(
            ainh, ainl, w1h + i*df, w1l + i*df, b1 + i*FF,
            nullptr, nullptr, ffnh, ffnl, FF, DD, 1);
        gemm_hmma3<<<dim3(8, 16), 256, GEMM_SMEM>>>(
            ffnh, ffnl, w2h + i*df, w2l + i*df, b2 + i*DD,
            h, h, nullptr, nullptr, DD, FF, 2);
    }
    layernorm_split<<<MROWS, 256>>>(h, lnfg, lnfb, ainh, ainl);
    gemm_hmma3<<<dim3(VV/128, 16), 256, GEMM_SMEM>>>(
        ainh, ainl, wouth, woutl, bout,
        nullptr, out, nullptr, nullptr, VV, DD, 0);
}